// round 5
// baseline (speedup 1.0000x reference)
#include <cuda_runtime.h>
#include <cuda_bf16.h>
#include <cstdint>
#include <math.h>

// Problem dims
#define BQ   128
#define TQ   512
#define HQ   512
#define N3   1536        // 3*H
#define D1   320         // LAT + F2
#define MROWS 65536      // B*T

// ---------------- scratch (__device__ globals; no runtime alloc) ----------------
__device__ __nv_bfloat16 g_Xhi[(size_t)MROWS * D1];
__device__ __nv_bfloat16 g_Xlo[(size_t)MROWS * D1];
__device__ float         g_xW [(size_t)MROWS * N3];      // reused for xW5 then xW6
__device__ __nv_bfloat16 g_g5hi[(size_t)MROWS * HQ];
__device__ __nv_bfloat16 g_g5lo[(size_t)MROWS * HQ];
__device__ __nv_bfloat16 g_g6hi[(size_t)MROWS * HQ];
__device__ __nv_bfloat16 g_g6lo[(size_t)MROWS * HQ];
__device__ __nv_bfloat16 g_W5t_hi[N3 * D1], g_W5t_lo[N3 * D1];   // [n][k]
__device__ __nv_bfloat16 g_U5t_hi[N3 * HQ], g_U5t_lo[N3 * HQ];
__device__ __nv_bfloat16 g_W6t_hi[N3 * HQ], g_W6t_lo[N3 * HQ];
__device__ __nv_bfloat16 g_U6t_hi[N3 * HQ], g_U6t_lo[N3 * HQ];
__device__ unsigned g_ctr[2];

// ---------------- helpers ----------------
__device__ __forceinline__ void bsplit(float v, __nv_bfloat16& hi, __nv_bfloat16& lo) {
    hi = __float2bfloat16_rn(v);
    lo = __float2bfloat16_rn(v - __bfloat162float(hi));
}
__device__ __forceinline__ float hsig(float x) {
    return fminf(fmaxf(0.2f * x + 0.5f, 0.0f), 1.0f);
}

#define MMA16816(C, A, Bf) asm volatile( \
    "mma.sync.aligned.m16n8k16.row.col.f32.bf16.bf16.f32 " \
    "{%0,%1,%2,%3},{%4,%5,%6,%7},{%8,%9},{%0,%1,%2,%3};\n" \
    : "+f"(C[0]), "+f"(C[1]), "+f"(C[2]), "+f"(C[3]) \
    : "r"(A[0]), "r"(A[1]), "r"(A[2]), "r"(A[3]), "r"(Bf[0]), "r"(Bf[1]))

// ---------------- prep: weight transposes + hi/lo split + counter reset ----------------
__global__ void prep_kernel(const float* __restrict__ W5, const float* __restrict__ U5,
                            const float* __restrict__ W6, const float* __restrict__ U6) {
    int i = blockIdx.x * blockDim.x + threadIdx.x;
    if (i == 0) { g_ctr[0] = 0u; g_ctr[1] = 0u; }
    const int nW5 = N3 * D1;        // 491520
    const int nU  = N3 * HQ;        // 786432
    if (i < nW5) {
        int n = i / D1, k = i % D1;
        bsplit(W5[k * N3 + n], g_W5t_hi[i], g_W5t_lo[i]);
    } else if (i < nW5 + nU) {
        int j = i - nW5; int n = j / HQ, k = j % HQ;
        bsplit(U5[k * N3 + n], g_U5t_hi[j], g_U5t_lo[j]);
    } else if (i < nW5 + 2 * nU) {
        int j = i - nW5 - nU; int n = j / HQ, k = j % HQ;
        bsplit(W6[k * N3 + n], g_W6t_hi[j], g_W6t_lo[j]);
    } else if (i < nW5 + 3 * nU) {
        int j = i - nW5 - 2 * nU; int n = j / HQ, k = j % HQ;
        bsplit(U6[k * N3 + n], g_U6t_hi[j], g_U6t_lo[j]);
    }
}

// ---------------- build X = concat(repeat(z), x2) * masks, split to bf16 hi/lo ----------------
__global__ void build_x_kernel(const float* __restrict__ z, const float* __restrict__ x2,
                               const float* __restrict__ masks) {
    int i = blockIdx.x * blockDim.x + threadIdx.x;
    if (i >= MROWS * D1) return;
    int row = i / D1, c = i % D1;
    int b = row >> 9;                 // T = 512
    float m = masks[row];
    float v = (c < 256) ? z[b * 256 + c] : x2[(size_t)row * 64 + (c - 256)];
    v *= m;
    bsplit(v, g_Xhi[i], g_Xlo[i]);
}

// ---------------- feedforward GEMM: g_xW = A(hi,lo) @ Wt(hi,lo)^T + bias ----------------
// phase 0: A = Xsplit (K=320), W = W5t, bias = bi5
// phase 1: A = g5split (K=512), W = W6t, bias = bi6
// Block tile 128(M) x 64(N), BK=16, 256 threads (8 warps, 4x2, warp tile 32x32)
__global__ void __launch_bounds__(256) gemm_ff(int phase, const float* __restrict__ bias) {
    const int K = phase ? HQ : D1;
    const __nv_bfloat16* Ahi = phase ? g_g5hi : g_Xhi;
    const __nv_bfloat16* Alo = phase ? g_g5lo : g_Xlo;
    const __nv_bfloat16* Whi = phase ? g_W6t_hi : g_W5t_hi;
    const __nv_bfloat16* Wlo = phase ? g_W6t_lo : g_W5t_lo;

    __shared__ __nv_bfloat16 sAh[128 * 24], sAl[128 * 24], sWh[64 * 24], sWl[64 * 24];

    int tid = threadIdx.x;
    int row0 = blockIdx.x * 128, n0 = blockIdx.y * 64;
    int warp = tid >> 5, lane = tid & 31, g = lane >> 2, tg = lane & 3;
    int wm = warp >> 1, wn = warp & 1;

    float C[2][4][4];
#pragma unroll
    for (int a = 0; a < 2; a++)
#pragma unroll
        for (int b = 0; b < 4; b++)
#pragma unroll
            for (int c = 0; c < 4; c++) C[a][b][c] = 0.0f;

    const int nk = K / 16;
    for (int kt = 0; kt < nk; kt++) {
        int k0 = kt * 16;
        {   // stage tiles (uint4 = 8 bf16)
            int r = tid >> 1, h = tid & 1;
            const uint4* pa = (const uint4*)Ahi + ((size_t)(row0 + r) * K + k0) / 8 + h;
            *(uint4*)((char*)sAh + r * 48 + h * 16) = *pa;
            const uint4* pb = (const uint4*)Alo + ((size_t)(row0 + r) * K + k0) / 8 + h;
            *(uint4*)((char*)sAl + r * 48 + h * 16) = *pb;
            if (tid < 128) {
                const uint4* pw = (const uint4*)Whi + ((size_t)(n0 + r) * K + k0) / 8 + h;
                *(uint4*)((char*)sWh + r * 48 + h * 16) = *pw;
                const uint4* pv = (const uint4*)Wlo + ((size_t)(n0 + r) * K + k0) / 8 + h;
                *(uint4*)((char*)sWl + r * 48 + h * 16) = *pv;
            }
        }
        __syncthreads();

        uint32_t ah[2][4], al[2][4], bh[4][2], bl[4][2];
#pragma unroll
        for (int mt = 0; mt < 2; mt++) {
            int m = wm * 32 + mt * 16 + g;
            ah[mt][0] = *(uint32_t*)((char*)sAh + m * 48 + tg * 4);
            ah[mt][1] = *(uint32_t*)((char*)sAh + (m + 8) * 48 + tg * 4);
            ah[mt][2] = *(uint32_t*)((char*)sAh + m * 48 + 16 + tg * 4);
            ah[mt][3] = *(uint32_t*)((char*)sAh + (m + 8) * 48 + 16 + tg * 4);
            al[mt][0] = *(uint32_t*)((char*)sAl + m * 48 + tg * 4);
            al[mt][1] = *(uint32_t*)((char*)sAl + (m + 8) * 48 + tg * 4);
            al[mt][2] = *(uint32_t*)((char*)sAl + m * 48 + 16 + tg * 4);
            al[mt][3] = *(uint32_t*)((char*)sAl + (m + 8) * 48 + 16 + tg * 4);
        }
#pragma unroll
        for (int nt = 0; nt < 4; nt++) {
            int n = wn * 32 + nt * 8 + g;
            bh[nt][0] = *(uint32_t*)((char*)sWh + n * 48 + tg * 4);
            bh[nt][1] = *(uint32_t*)((char*)sWh + n * 48 + 16 + tg * 4);
            bl[nt][0] = *(uint32_t*)((char*)sWl + n * 48 + tg * 4);
            bl[nt][1] = *(uint32_t*)((char*)sWl + n * 48 + 16 + tg * 4);
        }
#pragma unroll
        for (int mt = 0; mt < 2; mt++)
#pragma unroll
            for (int nt = 0; nt < 4; nt++) {
                MMA16816(C[mt][nt], ah[mt], bh[nt]);
                MMA16816(C[mt][nt], ah[mt], bl[nt]);
                MMA16816(C[mt][nt], al[mt], bh[nt]);
            }
        __syncthreads();
    }
    // epilogue: + bias, store fp32
#pragma unroll
    for (int mt = 0; mt < 2; mt++) {
#pragma unroll
        for (int nt = 0; nt < 4; nt++) {
            int m = row0 + wm * 32 + mt * 16 + g;
            int n = n0 + wn * 32 + nt * 8 + tg * 2;
            float b0v = bias[n], b1v = bias[n + 1];
            g_xW[(size_t)m * N3 + n]           = C[mt][nt][0] + b0v;
            g_xW[(size_t)m * N3 + n + 1]       = C[mt][nt][1] + b1v;
            g_xW[(size_t)(m + 8) * N3 + n]     = C[mt][nt][2] + b0v;
            g_xW[(size_t)(m + 8) * N3 + n + 1] = C[mt][nt][3] + b1v;
        }
    }
}

// ---------------- persistent GRU recurrence ----------------
// 128 blocks (8 batch tiles x 16 feature tiles), 384 threads (12 warps), 1 block/SM.
// smem: U hi (98304) | U lo (98304) | hs hi (16384) | hs lo (16384, aliased by inner)
#define SM_UHI 0
#define SM_ULO 98304
#define SM_HSH 196608
#define SM_HSL 212992
#define SM_TOTAL 229376
#define INNER_STRIDE 100

__global__ void __launch_bounds__(384, 1) gru_rec(int phase, const float* __restrict__ br) {
    extern __shared__ char sm[];
    const __nv_bfloat16* Uth = phase ? g_U6t_hi : g_U5t_hi;
    const __nv_bfloat16* Utl = phase ? g_U6t_lo : g_U5t_lo;
    const float* __restrict__ xW = g_xW;
    __nv_bfloat16* Ghi = phase ? g_g6hi : g_g5hi;
    __nv_bfloat16* Glo = phase ? g_g6lo : g_g5lo;
    unsigned* ctr = &g_ctr[phase];

    const int tid = threadIdx.x;
    const int warp = tid >> 5, lane = tid & 31;
    const int g = lane >> 2, tg = lane & 3;
    const int bb = (int)blockIdx.x >> 4, fb = (int)blockIdx.x & 15;
    const int b0 = bb * 16, f0 = fb * 32;
    const int gi = warp >> 2, ct = warp & 3;        // gate id, 8-col group

    // ---- preload U slice: 96 rows (3 gates x 32 cols) x 512 K, hi+lo, XOR swizzled
    for (int idx = tid; idx < 2 * 96 * 64; idx += 384) {
        int arr = idx >= 96 * 64;
        int e = arr ? (idx - 96 * 64) : idx;
        int j = e >> 6;              // smem row 0..95
        int q = e & 63;              // uint4 within row
        int w = q << 2;              // word index
        int sw = w ^ ((j & 7) << 2);
        int n = (j >> 5) * HQ + f0 + (j & 31);   // global col in 0..1535
        uint4 v = ((const uint4*)((arr ? Utl : Uth) + (size_t)n * HQ))[q];
        *(uint4*)(sm + (arr ? SM_ULO : SM_UHI) + j * 1024 + sw * 4) = v;
    }
    // per-thread combine constants (biases)
    float bzv[2], brv[2], bhv[2];
#pragma unroll
    for (int s = 0; s < 2; s++) {
        int e = tid + s * 384;
        if (e < 512) {
            int f = f0 + (e & 31);
            bzv[s] = br[f]; brv[s] = br[512 + f]; bhv[s] = br[1024 + f];
        } else { bzv[s] = brv[s] = bhv[s] = 0.f; }
    }
    __syncthreads();

    const int jrow = gi * 32 + ct * 8 + g;          // my B row in smem U
    char* uh = sm + SM_UHI + jrow * 1024;
    char* ul = sm + SM_ULO + jrow * 1024;
    const int swz = g << 2;

    for (int t = 0; t < TQ; t++) {
        // ---- stage h_{t-1}: 16 rows x 512 bf16, hi+lo
        if (t == 0) {
            for (int idx = tid; idx < 2048; idx += 384) {
                int arr = idx >> 10, e = idx & 1023, r = e >> 6, q = e & 63;
                int sw = (q << 2) ^ ((r & 7) << 2);
                *(uint4*)(sm + (arr ? SM_HSL : SM_HSH) + r * 1024 + sw * 4) =
                    make_uint4(0u, 0u, 0u, 0u);
            }
        } else {
            for (int idx = tid; idx < 2048; idx += 384) {
                int arr = idx >> 10, e = idx & 1023, r = e >> 6, q = e & 63;
                int sw = (q << 2) ^ ((r & 7) << 2);
                const __nv_bfloat16* src =
                    (arr ? Glo : Ghi) + ((size_t)(b0 + r) * TQ + (t - 1)) * HQ;
                uint4 v = __ldcg((const uint4*)src + q);
                *(uint4*)(sm + (arr ? SM_HSL : SM_HSH) + r * 1024 + sw * 4) = v;
            }
        }
        __syncthreads();

        // ---- prefetch xW + h_prev for combine (hides gmem latency under MMA)
        float xzv[2], xrv[2], xhv[2], hpv[2];
#pragma unroll
        for (int s = 0; s < 2; s++) {
            int e = tid + s * 384;
            if (e < 512) {
                int r = e >> 5, c = e & 31;
                size_t row = (size_t)(b0 + r) * TQ + t;
                int f = f0 + c;
                xzv[s] = xW[row * N3 + f];
                xrv[s] = xW[row * N3 + 512 + f];
                xhv[s] = xW[row * N3 + 1024 + f];
                // FIX: h_prev column is the GLOBAL feature index f0+c, not c
                int w = (f0 + c) >> 1;
                int sw = w ^ ((r & 7) << 2);
                uint32_t whi = *(uint32_t*)(sm + SM_HSH + r * 1024 + sw * 4);
                uint32_t wlo = *(uint32_t*)(sm + SM_HSL + r * 1024 + sw * 4);
                unsigned short sh = (c & 1) ? (unsigned short)(whi >> 16) : (unsigned short)(whi & 0xffff);
                unsigned short sl = (c & 1) ? (unsigned short)(wlo >> 16) : (unsigned short)(wlo & 0xffff);
                hpv[s] = __bfloat162float(__ushort_as_bfloat16(sh)) +
                         __bfloat162float(__ushort_as_bfloat16(sl));
            } else { xzv[s] = xrv[s] = xhv[s] = hpv[s] = 0.f; }
        }

        // ---- MMA: inner[16 x 96] = h_prev @ U  (3-pass bf16 split)
        float C[4] = {0.f, 0.f, 0.f, 0.f};
#pragma unroll 4
        for (int kt = 0; kt < 32; kt++) {
            int w0 = kt * 8 + tg;
            int sw0 = w0 ^ swz, sw1 = (w0 + 4) ^ swz;
            uint32_t a[4], al2[4], bhr[2], blr[2];
            a[0]  = *(uint32_t*)(sm + SM_HSH + g * 1024 + sw0 * 4);
            a[1]  = *(uint32_t*)(sm + SM_HSH + (g + 8) * 1024 + sw0 * 4);
            a[2]  = *(uint32_t*)(sm + SM_HSH + g * 1024 + sw1 * 4);
            a[3]  = *(uint32_t*)(sm + SM_HSH + (g + 8) * 1024 + sw1 * 4);
            al2[0] = *(uint32_t*)(sm + SM_HSL + g * 1024 + sw0 * 4);
            al2[1] = *(uint32_t*)(sm + SM_HSL + (g + 8) * 1024 + sw0 * 4);
            al2[2] = *(uint32_t*)(sm + SM_HSL + g * 1024 + sw1 * 4);
            al2[3] = *(uint32_t*)(sm + SM_HSL + (g + 8) * 1024 + sw1 * 4);
            bhr[0] = *(uint32_t*)(uh + sw0 * 4);
            bhr[1] = *(uint32_t*)(uh + sw1 * 4);
            blr[0] = *(uint32_t*)(ul + sw0 * 4);
            blr[1] = *(uint32_t*)(ul + sw1 * 4);
            MMA16816(C, a, bhr);
            MMA16816(C, a, blr);
            MMA16816(C, al2, bhr);
        }
        __syncthreads();   // all reads of hs done (hprev read + MMA)

        // ---- exchange: write C into inner buffer aliased over hs_lo
        {
            float* inner = (float*)(sm + SM_HSL);
            int col = gi * 32 + ct * 8 + 2 * tg;
            inner[g * INNER_STRIDE + col]           = C[0];
            inner[g * INNER_STRIDE + col + 1]       = C[1];
            inner[(g + 8) * INNER_STRIDE + col]     = C[2];
            inner[(g + 8) * INNER_STRIDE + col + 1] = C[3];
        }
        __syncthreads();

        // ---- gates + h_new, write to gmem (time-indexed: no WAR)
#pragma unroll
        for (int s = 0; s < 2; s++) {
            int e = tid + s * 384;
            if (e < 512) {
                int r = e >> 5, c = e & 31;
                const float* inner = (const float*)(sm + SM_HSL);
                float iz = inner[r * INNER_STRIDE + c];
                float ir = inner[r * INNER_STRIDE + 32 + c];
                float ih = inner[r * INNER_STRIDE + 64 + c];
                float zg = hsig(xzv[s] + iz + bzv[s]);
                float rg = hsig(xrv[s] + ir + brv[s]);
                float hh = tanhf(xhv[s] + rg * (ih + bhv[s]));
                float hn = zg * hpv[s] + (1.0f - zg) * hh;
                size_t row = (size_t)(b0 + r) * TQ + t;
                __nv_bfloat16 hi, lo; bsplit(hn, hi, lo);
                Ghi[row * HQ + f0 + c] = hi;
                Glo[row * HQ + f0 + c] = lo;
            }
        }
        __threadfence();
        __syncthreads();
        // ---- grid barrier (monotonic counter; all 128 blocks resident)
        if (tid == 0) {
            atomicAdd(ctr, 1u);
            unsigned target = (unsigned)(t + 1) * 128u;
            unsigned v;
            do {
                asm volatile("ld.acquire.gpu.u32 %0, [%1];" : "=r"(v) : "l"(ctr));
                if (v >= target) break;
                __nanosleep(32);
            } while (true);
        }
        __syncthreads();
    }
}

// ---------------- final dense(1) + tanh + mask ----------------
__global__ void __launch_bounds__(256) dense_out(const float* __restrict__ Wd,
                                                 const float* __restrict__ bd,
                                                 const float* __restrict__ dmask,
                                                 float* __restrict__ out) {
    __shared__ float w[512];
    int tid = threadIdx.x;
    for (int i = tid; i < 512; i += 256) w[i] = Wd[i];
    __syncthreads();
    int warp = tid >> 5, lane = tid & 31;
    size_t row = (size_t)blockIdx.x * 8 + warp;
    const __nv_bfloat16* ph = g_g6hi + row * HQ;
    const __nv_bfloat16* pl = g_g6lo + row * HQ;
    float s = 0.f;
#pragma unroll 4
    for (int i = lane; i < 512; i += 32)
        s += (__bfloat162float(ph[i]) + __bfloat162float(pl[i])) * w[i];
#pragma unroll
    for (int o = 16; o; o >>= 1) s += __shfl_xor_sync(0xffffffffu, s, o);
    if (lane == 0) out[row] = tanhf(s + bd[0]) * dmask[row];
}

// ---------------- launch ----------------
extern "C" void kernel_launch(void* const* d_in, const int* in_sizes, int n_in,
                              void* d_out, int out_size) {
    const float* z   = (const float*)d_in[0];
    const float* x2  = (const float*)d_in[1];
    const float* msk = (const float*)d_in[2];
    const float* dmk = (const float*)d_in[3];
    const float* W5  = (const float*)d_in[4];
    const float* U5  = (const float*)d_in[5];
    const float* bi5 = (const float*)d_in[6];
    const float* br5 = (const float*)d_in[7];
    const float* W6  = (const float*)d_in[8];
    const float* U6  = (const float*)d_in[9];
    const float* bi6 = (const float*)d_in[10];
    const float* br6 = (const float*)d_in[11];
    const float* Wd  = (const float*)d_in[12];
    const float* bd  = (const float*)d_in[13];
    float* out = (float*)d_out;

    cudaFuncSetAttribute(gru_rec, cudaFuncAttributeMaxDynamicSharedMemorySize, SM_TOTAL);

    prep_kernel<<<11136, 256>>>(W5, U5, W6, U6);
    build_x_kernel<<<81920, 256>>>(z, x2, msk);
    gemm_ff<<<dim3(512, 24), 256>>>(0, bi5);
    gru_rec<<<128, 384, SM_TOTAL>>>(0, br5);
    gemm_ff<<<dim3(512, 24), 256>>>(1, bi6);
    gru_rec<<<128, 384, SM_TOTAL>>>(1, br6);
    dense_out<<<8192, 256>>>(Wd, bd, dmk, out);
}

// round 9
// speedup vs baseline: 1.0528x; 1.0528x over previous
#include <cuda_runtime.h>
#include <cuda_bf16.h>
#include <cstdint>
#include <math.h>

// Problem dims
#define BQ   128
#define TQ   512
#define HQ   512
#define N3   1536        // 3*H
#define D1   320         // LAT + F2
#define MROWS 65536      // B*T

// ---------------- scratch (__device__ globals; no runtime alloc) ----------------
__device__ __nv_bfloat16 g_Xhi[(size_t)MROWS * D1];
__device__ __nv_bfloat16 g_Xlo[(size_t)MROWS * D1];
__device__ float         g_xW [(size_t)MROWS * N3];      // reused for xW5 then xW6
__device__ __nv_bfloat16 g_g5hi[(size_t)MROWS * HQ];
__device__ __nv_bfloat16 g_g5lo[(size_t)MROWS * HQ];
__device__ __nv_bfloat16 g_g6hi[(size_t)MROWS * HQ];
__device__ __nv_bfloat16 g_g6lo[(size_t)MROWS * HQ];
__device__ __nv_bfloat16 g_W5t_hi[N3 * D1], g_W5t_lo[N3 * D1];   // [n][k]
__device__ __nv_bfloat16 g_U5t_hi[N3 * HQ], g_U5t_lo[N3 * HQ];
__device__ __nv_bfloat16 g_W6t_hi[N3 * HQ], g_W6t_lo[N3 * HQ];
__device__ __nv_bfloat16 g_U6t_hi[N3 * HQ], g_U6t_lo[N3 * HQ];
__device__ unsigned g_ctr2[2][8];      // per (phase, batch-group) barrier counters

// ---------------- helpers ----------------
__device__ __forceinline__ void bsplit(float v, __nv_bfloat16& hi, __nv_bfloat16& lo) {
    hi = __float2bfloat16_rn(v);
    lo = __float2bfloat16_rn(v - __bfloat162float(hi));
}
__device__ __forceinline__ float hsig(float x) {
    return fminf(fmaxf(0.2f * x + 0.5f, 0.0f), 1.0f);
}

#define MMA16816(C, A, Bf) asm volatile( \
    "mma.sync.aligned.m16n8k16.row.col.f32.bf16.bf16.f32 " \
    "{%0,%1,%2,%3},{%4,%5,%6,%7},{%8,%9},{%0,%1,%2,%3};\n" \
    : "+f"(C[0]), "+f"(C[1]), "+f"(C[2]), "+f"(C[3]) \
    : "r"(A[0]), "r"(A[1]), "r"(A[2]), "r"(A[3]), "r"((Bf)[0]), "r"((Bf)[1]))

#define LDSM4(R, ADDR) asm volatile( \
    "ldmatrix.sync.aligned.m8n8.x4.shared.b16 {%0,%1,%2,%3}, [%4];" \
    : "=r"((R)[0]), "=r"((R)[1]), "=r"((R)[2]), "=r"((R)[3]) : "r"(ADDR))

// ---------------- prep: weight transposes + hi/lo split + counter reset ----------------
__global__ void prep_kernel(const float* __restrict__ W5, const float* __restrict__ U5,
                            const float* __restrict__ W6, const float* __restrict__ U6) {
    int i = blockIdx.x * blockDim.x + threadIdx.x;
    if (i < 16) ((unsigned*)g_ctr2)[i] = 0u;
    const int nW5 = N3 * D1;        // 491520
    const int nU  = N3 * HQ;        // 786432
    if (i < nW5) {
        int n = i / D1, k = i % D1;
        bsplit(W5[k * N3 + n], g_W5t_hi[i], g_W5t_lo[i]);
    } else if (i < nW5 + nU) {
        int j = i - nW5; int n = j / HQ, k = j % HQ;
        bsplit(U5[k * N3 + n], g_U5t_hi[j], g_U5t_lo[j]);
    } else if (i < nW5 + 2 * nU) {
        int j = i - nW5 - nU; int n = j / HQ, k = j % HQ;
        bsplit(W6[k * N3 + n], g_W6t_hi[j], g_W6t_lo[j]);
    } else if (i < nW5 + 3 * nU) {
        int j = i - nW5 - 2 * nU; int n = j / HQ, k = j % HQ;
        bsplit(U6[k * N3 + n], g_U6t_hi[j], g_U6t_lo[j]);
    }
}

// ---------------- build X = concat(repeat(z), x2) * masks, split to bf16 hi/lo ----------------
__global__ void build_x_kernel(const float* __restrict__ z, const float* __restrict__ x2,
                               const float* __restrict__ masks) {
    int i = blockIdx.x * blockDim.x + threadIdx.x;
    if (i >= MROWS * D1) return;
    int row = i / D1, c = i % D1;
    int b = row >> 9;                 // T = 512
    float m = masks[row];
    float v = (c < 256) ? z[b * 256 + c] : x2[(size_t)row * 64 + (c - 256)];
    v *= m;
    bsplit(v, g_Xhi[i], g_Xlo[i]);
}

// ---------------- feedforward GEMM: g_xW = A(hi,lo) @ Wt(hi,lo)^T + bias ----------------
// Block tile 128(M) x 64(N), BK=16, 256 threads (8 warps, 4x2, warp tile 32x32)
// Register-prefetch pipeline: next K-tile's LDGs issue right after the staging
// sync, overlapping the gmem latency with this tile's MMAs.
__global__ void __launch_bounds__(256) gemm_ff(int phase, const float* __restrict__ bias) {
    const int K = phase ? HQ : D1;
    const __nv_bfloat16* Ahi = phase ? g_g5hi : g_Xhi;
    const __nv_bfloat16* Alo = phase ? g_g5lo : g_Xlo;
    const __nv_bfloat16* Whi = phase ? g_W6t_hi : g_W5t_hi;
    const __nv_bfloat16* Wlo = phase ? g_W6t_lo : g_W5t_lo;

    __shared__ __nv_bfloat16 sAh[128 * 24], sAl[128 * 24], sWh[64 * 24], sWl[64 * 24];

    int tid = threadIdx.x;
    int row0 = blockIdx.x * 128, n0 = blockIdx.y * 64;
    int warp = tid >> 5, lane = tid & 31, g = lane >> 2, tg = lane & 3;
    int wm = warp >> 1, wn = warp & 1;
    int r = tid >> 1, h = tid & 1;

    float C[2][4][4];
#pragma unroll
    for (int a = 0; a < 2; a++)
#pragma unroll
        for (int b = 0; b < 4; b++)
#pragma unroll
            for (int c = 0; c < 4; c++) C[a][b][c] = 0.0f;

    const int nk = K / 16;
    uint4 ra, rb, rw, rv;

#define FF_LOAD(KT) do { \
        int k0 = (KT) * 16; \
        ra = *((const uint4*)Ahi + ((size_t)(row0 + r) * K + k0) / 8 + h); \
        rb = *((const uint4*)Alo + ((size_t)(row0 + r) * K + k0) / 8 + h); \
        if (tid < 128) { \
            rw = *((const uint4*)Whi + ((size_t)(n0 + r) * K + k0) / 8 + h); \
            rv = *((const uint4*)Wlo + ((size_t)(n0 + r) * K + k0) / 8 + h); \
        } \
    } while (0)

    FF_LOAD(0);
    for (int kt = 0; kt < nk; kt++) {
        // stage current tile from regs
        *(uint4*)((char*)sAh + r * 48 + h * 16) = ra;
        *(uint4*)((char*)sAl + r * 48 + h * 16) = rb;
        if (tid < 128) {
            *(uint4*)((char*)sWh + r * 48 + h * 16) = rw;
            *(uint4*)((char*)sWl + r * 48 + h * 16) = rv;
        }
        __syncthreads();
        if (kt + 1 < nk) FF_LOAD(kt + 1);   // overlaps MMAs below

        uint32_t ah[2][4], al[2][4], bh[4][2], bl[4][2];
#pragma unroll
        for (int mt = 0; mt < 2; mt++) {
            int m = wm * 32 + mt * 16 + g;
            ah[mt][0] = *(uint32_t*)((char*)sAh + m * 48 + tg * 4);
            ah[mt][1] = *(uint32_t*)((char*)sAh + (m + 8) * 48 + tg * 4);
            ah[mt][2] = *(uint32_t*)((char*)sAh + m * 48 + 16 + tg * 4);
            ah[mt][3] = *(uint32_t*)((char*)sAh + (m + 8) * 48 + 16 + tg * 4);
            al[mt][0] = *(uint32_t*)((char*)sAl + m * 48 + tg * 4);
            al[mt][1] = *(uint32_t*)((char*)sAl + (m + 8) * 48 + tg * 4);
            al[mt][2] = *(uint32_t*)((char*)sAl + m * 48 + 16 + tg * 4);
            al[mt][3] = *(uint32_t*)((char*)sAl + (m + 8) * 48 + 16 + tg * 4);
        }
#pragma unroll
        for (int nt = 0; nt < 4; nt++) {
            int n = wn * 32 + nt * 8 + g;
            bh[nt][0] = *(uint32_t*)((char*)sWh + n * 48 + tg * 4);
            bh[nt][1] = *(uint32_t*)((char*)sWh + n * 48 + 16 + tg * 4);
            bl[nt][0] = *(uint32_t*)((char*)sWl + n * 48 + tg * 4);
            bl[nt][1] = *(uint32_t*)((char*)sWl + n * 48 + 16 + tg * 4);
        }
#pragma unroll
        for (int mt = 0; mt < 2; mt++)
#pragma unroll
            for (int nt = 0; nt < 4; nt++) {
                MMA16816(C[mt][nt], ah[mt], bh[nt]);
                MMA16816(C[mt][nt], ah[mt], bl[nt]);
                MMA16816(C[mt][nt], al[mt], bh[nt]);
            }
        __syncthreads();
    }
    // epilogue: + bias, store fp32
#pragma unroll
    for (int mt = 0; mt < 2; mt++) {
#pragma unroll
        for (int nt = 0; nt < 4; nt++) {
            int m = row0 + wm * 32 + mt * 16 + g;
            int n = n0 + wn * 32 + nt * 8 + tg * 2;
            float b0v = bias[n], b1v = bias[n + 1];
            g_xW[(size_t)m * N3 + n]           = C[mt][nt][0] + b0v;
            g_xW[(size_t)m * N3 + n + 1]       = C[mt][nt][1] + b1v;
            g_xW[(size_t)(m + 8) * N3 + n]     = C[mt][nt][2] + b0v;
            g_xW[(size_t)(m + 8) * N3 + n + 1] = C[mt][nt][3] + b1v;
        }
    }
}

// ---------------- persistent GRU recurrence ----------------
// 128 blocks (8 batch tiles x 16 feature tiles), 384 threads (12 warps), 1 block/SM.
// Warp partition: ks (K half, 2) x gate (3) x n-half (2x16 cols).
// Fragments via ldmatrix.x4; two K-partials combined through smem inner buffers.
// smem: U hi (98304) | U lo (98304) | hs hi (16384) | hs lo (16384, aliased by inner[2])
#define SM_UHI 0
#define SM_ULO 98304
#define SM_HSH 196608
#define SM_HSL 212992
#define SM_TOTAL 229376
#define INNER_STRIDE 100
#define INNER_BYTES  6400     // 16 rows * 100 floats * 4

__global__ void __launch_bounds__(384, 1) gru_rec(int phase, const float* __restrict__ br) {
    extern __shared__ char sm[];
    const __nv_bfloat16* Uth = phase ? g_U6t_hi : g_U5t_hi;
    const __nv_bfloat16* Utl = phase ? g_U6t_lo : g_U5t_lo;
    const float* __restrict__ xW = g_xW;
    __nv_bfloat16* Ghi = phase ? g_g6hi : g_g5hi;
    __nv_bfloat16* Glo = phase ? g_g6lo : g_g5lo;

    const int tid = threadIdx.x;
    const int warp = tid >> 5, lane = tid & 31;
    const int g = lane >> 2, tg = lane & 3;
    const int bb = (int)blockIdx.x >> 4, fb = (int)blockIdx.x & 15;
    const int b0 = bb * 16, f0 = fb * 32;
    unsigned* ctr = &g_ctr2[phase][bb];

    // warp roles
    const int ks  = warp / 6;            // K half: kt in [ks*16, ks*16+16)
    const int w6  = warp % 6;
    const int gi2 = w6 >> 1;             // gate 0..2
    const int nh  = w6 & 1;              // n half (16 cols)
    const int rm  = lane & 7;
    const int jq  = lane >> 3;           // ldmatrix matrix id 0..3
    const int arow = rm + ((jq & 1) << 3);       // A: j0/j2 rows 0-7, j1/j3 rows 8-15
    const int ahh  = jq >> 1;                    // A: k half (j0,j1 -> k0-7; j2,j3 -> k8-15)
    const int brow = rm + ((jq >> 1) << 3);      // B: j0/j1 n 0-7, j2/j3 n 8-15
    const int bkk  = jq & 1;                     // B: k half
    const int jrow0 = gi2 * 32 + nh * 16;

    const unsigned sm32 = (unsigned)__cvta_generic_to_shared(sm);
    const unsigned aBaseH = sm32 + SM_HSH + arow * 1024;
    const unsigned aBaseL = sm32 + SM_HSL + arow * 1024;
    const unsigned bBaseH = sm32 + SM_UHI + (jrow0 + brow) * 1024;
    const unsigned bBaseL = sm32 + SM_ULO + (jrow0 + brow) * 1024;

    // ---- preload U slice: 96 rows (3 gates x 32 cols) x 512 K, hi+lo, 16B-chunk swizzle
    for (int idx = tid; idx < 2 * 96 * 64; idx += 384) {
        int arr = idx >= 96 * 64;
        int e = arr ? (idx - 96 * 64) : idx;
        int j = e >> 6;              // smem row 0..95
        int q = e & 63;              // 16B chunk within row
        int sw = q ^ (j & 7);
        int n = (j >> 5) * HQ + f0 + (j & 31);   // global col in 0..1535
        uint4 v = ((const uint4*)((arr ? Utl : Uth) + (size_t)n * HQ))[q];
        *(uint4*)(sm + (arr ? SM_ULO : SM_UHI) + j * 1024 + sw * 16) = v;
    }
    // per-thread combine constants (biases)
    float bzv[2], brv[2], bhv[2];
#pragma unroll
    for (int s = 0; s < 2; s++) {
        int e = tid + s * 384;
        if (e < 512) {
            int f = f0 + (e & 31);
            bzv[s] = br[f]; brv[s] = br[512 + f]; bhv[s] = br[1024 + f];
        } else { bzv[s] = brv[s] = bhv[s] = 0.f; }
    }
    __syncthreads();

    for (int t = 0; t < TQ; t++) {
        // ---- prefetch xW for combine (independent of staging; overlaps LDGs)
        float xzv[2], xrv[2], xhv[2], hpv[2];
#pragma unroll
        for (int s = 0; s < 2; s++) {
            int e = tid + s * 384;
            if (e < 512) {
                int r = e >> 5, c = e & 31;
                size_t row = (size_t)(b0 + r) * TQ + t;
                int f = f0 + c;
                xzv[s] = xW[row * N3 + f];
                xrv[s] = xW[row * N3 + 512 + f];
                xhv[s] = xW[row * N3 + 1024 + f];
            } else { xzv[s] = xrv[s] = xhv[s] = 0.f; }
            hpv[s] = 0.f;
        }

        // ---- stage h_{t-1}: 16 rows x 512 bf16, hi+lo
        if (t == 0) {
            for (int idx = tid; idx < 2048; idx += 384) {
                int arr = idx >> 10, e = idx & 1023, r = e >> 6, q = e & 63;
                int sw = q ^ (r & 7);
                *(uint4*)(sm + (arr ? SM_HSL : SM_HSH) + r * 1024 + sw * 16) =
                    make_uint4(0u, 0u, 0u, 0u);
            }
        } else {
            for (int idx = tid; idx < 2048; idx += 384) {
                int arr = idx >> 10, e = idx & 1023, r = e >> 6, q = e & 63;
                int sw = q ^ (r & 7);
                const __nv_bfloat16* src =
                    (arr ? Glo : Ghi) + ((size_t)(b0 + r) * TQ + (t - 1)) * HQ;
                uint4 v = __ldcg((const uint4*)src + q);
                *(uint4*)(sm + (arr ? SM_HSL : SM_HSH) + r * 1024 + sw * 16) = v;
            }
        }
        __syncthreads();

        // ---- h_prev values for the blend (global feature index f0+c)
#pragma unroll
        for (int s = 0; s < 2; s++) {
            int e = tid + s * 384;
            if (e < 512) {
                int r = e >> 5, c = e & 31;
                int w = (f0 + c) >> 1;
                int sw = w ^ ((r & 7) << 2);
                uint32_t whi = *(uint32_t*)(sm + SM_HSH + r * 1024 + sw * 4);
                uint32_t wlo = *(uint32_t*)(sm + SM_HSL + r * 1024 + sw * 4);
                unsigned short sh = (c & 1) ? (unsigned short)(whi >> 16) : (unsigned short)(whi & 0xffff);
                unsigned short sl = (c & 1) ? (unsigned short)(wlo >> 16) : (unsigned short)(wlo & 0xffff);
                hpv[s] = __bfloat162float(__ushort_as_bfloat16(sh)) +
                         __bfloat162float(__ushort_as_bfloat16(sl));
            }
        }

        // ---- MMA: partial inner[16 x 96] over my K half (3-pass bf16 split, ldmatrix)
        float C0[4] = {0.f, 0.f, 0.f, 0.f}, C1[4] = {0.f, 0.f, 0.f, 0.f};
        const int ktBeg = ks * 16, ktEnd = ktBeg + 16;
#pragma unroll 4
        for (int kt = ktBeg; kt < ktEnd; kt++) {
            unsigned aOff = (unsigned)(((2 * kt + ahh) ^ rm) * 16);
            unsigned bOff = (unsigned)(((2 * kt + bkk) ^ rm) * 16);
            uint32_t ah4[4], al4[4], bh4[4], bl4[4];
            LDSM4(ah4, aBaseH + aOff);
            LDSM4(al4, aBaseL + aOff);
            LDSM4(bh4, bBaseH + bOff);
            LDSM4(bl4, bBaseL + bOff);
            MMA16816(C0, ah4, bh4);
            MMA16816(C0, ah4, bl4);
            MMA16816(C0, al4, bh4);
            MMA16816(C1, ah4, bh4 + 2);
            MMA16816(C1, ah4, bl4 + 2);
            MMA16816(C1, al4, bh4 + 2);
        }
        __syncthreads();   // all reads of hs done (hprev + ldmatrix)

        // ---- exchange: write K-partials into inner buffers aliased over hs_lo
        {
            float* innerK = (float*)(sm + SM_HSL + ks * INNER_BYTES);
            int colb = gi2 * 32 + nh * 16 + 2 * tg;
            innerK[g * INNER_STRIDE + colb]            = C0[0];
            innerK[g * INNER_STRIDE + colb + 1]        = C0[1];
            innerK[(g + 8) * INNER_STRIDE + colb]      = C0[2];
            innerK[(g + 8) * INNER_STRIDE + colb + 1]  = C0[3];
            innerK[g * INNER_STRIDE + colb + 8]        = C1[0];
            innerK[g * INNER_STRIDE + colb + 9]        = C1[1];
            innerK[(g + 8) * INNER_STRIDE + colb + 8]  = C1[2];
            innerK[(g + 8) * INNER_STRIDE + colb + 9]  = C1[3];
        }
        __syncthreads();

        // ---- gates + h_new, write to gmem (time-indexed: no WAR)
#pragma unroll
        for (int s = 0; s < 2; s++) {
            int e = tid + s * 384;
            if (e < 512) {
                int r = e >> 5, c = e & 31;
                const float* in0 = (const float*)(sm + SM_HSL);
                const float* in1 = (const float*)(sm + SM_HSL + INNER_BYTES);
                float iz = in0[r * INNER_STRIDE + c]      + in1[r * INNER_STRIDE + c];
                float ir = in0[r * INNER_STRIDE + 32 + c] + in1[r * INNER_STRIDE + 32 + c];
                float ih = in0[r * INNER_STRIDE + 64 + c] + in1[r * INNER_STRIDE + 64 + c];
                float zg = hsig(xzv[s] + iz + bzv[s]);
                float rg = hsig(xrv[s] + ir + brv[s]);
                float hh = tanhf(xhv[s] + rg * (ih + bhv[s]));
                float hn = zg * hpv[s] + (1.0f - zg) * hh;
                size_t row = (size_t)(b0 + r) * TQ + t;
                __nv_bfloat16 hi, lo; bsplit(hn, hi, lo);
                Ghi[row * HQ + f0 + c] = hi;
                Glo[row * HQ + f0 + c] = lo;
            }
        }
        __threadfence();
        __syncthreads();
        // ---- per-batch-group barrier (16 feature blocks share one bb)
        if (tid == 0) {
            atomicAdd(ctr, 1u);
            unsigned target = (unsigned)(t + 1) * 16u;
            unsigned v;
            do {
                asm volatile("ld.acquire.gpu.u32 %0, [%1];" : "=r"(v) : "l"(ctr));
                if (v >= target) break;
                __nanosleep(32);
            } while (true);
        }
        __syncthreads();
    }
}

// ---------------- final dense(1) + tanh + mask ----------------
__global__ void __launch_bounds__(256) dense_out(const float* __restrict__ Wd,
                                                 const float* __restrict__ bd,
                                                 const float* __restrict__ dmask,
                                                 float* __restrict__ out) {
    __shared__ float w[512];
    int tid = threadIdx.x;
    for (int i = tid; i < 512; i += 256) w[i] = Wd[i];
    __syncthreads();
    int warp = tid >> 5, lane = tid & 31;
    size_t row = (size_t)blockIdx.x * 8 + warp;
    const __nv_bfloat16* ph = g_g6hi + row * HQ;
    const __nv_bfloat16* pl = g_g6lo + row * HQ;
    float s = 0.f;
#pragma unroll 4
    for (int i = lane; i < 512; i += 32)
        s += (__bfloat162float(ph[i]) + __bfloat162float(pl[i])) * w[i];
#pragma unroll
    for (int o = 16; o; o >>= 1) s += __shfl_xor_sync(0xffffffffu, s, o);
    if (lane == 0) out[row] = tanhf(s + bd[0]) * dmask[row];
}

// ---------------- launch ----------------
extern "C" void kernel_launch(void* const* d_in, const int* in_sizes, int n_in,
                              void* d_out, int out_size) {
    const float* z   = (const float*)d_in[0];
    const float* x2  = (const float*)d_in[1];
    const float* msk = (const float*)d_in[2];
    const float* dmk = (const float*)d_in[3];
    const float* W5  = (const float*)d_in[4];
    const float* U5  = (const float*)d_in[5];
    const float* bi5 = (const float*)d_in[6];
    const float* br5 = (const float*)d_in[7];
    const float* W6  = (const float*)d_in[8];
    const float* U6  = (const float*)d_in[9];
    const float* bi6 = (const float*)d_in[10];
    const float* br6 = (const float*)d_in[11];
    const float* Wd  = (const float*)d_in[12];
    const float* bd  = (const float*)d_in[13];
    float* out = (float*)d_out;

    cudaFuncSetAttribute(gru_rec, cudaFuncAttributeMaxDynamicSharedMemorySize, SM_TOTAL);

    prep_kernel<<<11136, 256>>>(W5, U5, W6, U6);
    build_x_kernel<<<81920, 256>>>(z, x2, msk);
    gemm_ff<<<dim3(512, 24), 256>>>(0, bi5);
    gru_rec<<<128, 384, SM_TOTAL>>>(0, br5);
    gemm_ff<<<dim3(512, 24), 256>>>(1, bi6);
    gru_rec<<<128, 384, SM_TOTAL>>>(1, br6);
    dense_out<<<8192, 256>>>(Wd, bd, dmk, out);
}

// round 11
// speedup vs baseline: 1.1364x; 1.0795x over previous
#include <cuda_runtime.h>
#include <cuda_bf16.h>
#include <cstdint>
#include <math.h>

// Problem dims
#define BQ   128
#define TQ   512
#define HQ   512
#define N3   1536        // 3*H
#define D1   320         // LAT + F2
#define MROWS 65536      // B*T

// ---------------- scratch (__device__ globals; no runtime alloc) ----------------
__device__ __nv_bfloat16 g_Xhi[(size_t)MROWS * D1];
__device__ __nv_bfloat16 g_Xlo[(size_t)MROWS * D1];
__device__ float         g_xW [(size_t)MROWS * N3];      // reused for xW5 then xW6
__device__ __nv_bfloat16 g_g5hi[(size_t)MROWS * HQ];
__device__ __nv_bfloat16 g_g5lo[(size_t)MROWS * HQ];
__device__ __nv_bfloat16 g_g6hi[(size_t)MROWS * HQ];
__device__ __nv_bfloat16 g_g6lo[(size_t)MROWS * HQ];
__device__ __nv_bfloat16 g_W5t_hi[N3 * D1], g_W5t_lo[N3 * D1];   // [n][k]
__device__ __nv_bfloat16 g_U5t_hi[N3 * HQ], g_U5t_lo[N3 * HQ];
__device__ __nv_bfloat16 g_W6t_hi[N3 * HQ], g_W6t_lo[N3 * HQ];
__device__ __nv_bfloat16 g_U6t_hi[N3 * HQ], g_U6t_lo[N3 * HQ];
__device__ unsigned g_ctr2[2][8];      // per (phase, batch-group) barrier counters

// ---------------- helpers ----------------
__device__ __forceinline__ void bsplit(float v, __nv_bfloat16& hi, __nv_bfloat16& lo) {
    hi = __float2bfloat16_rn(v);
    lo = __float2bfloat16_rn(v - __bfloat162float(hi));
}
__device__ __forceinline__ float hsig(float x) {
    return fminf(fmaxf(0.2f * x + 0.5f, 0.0f), 1.0f);
}

#define MMA16816(C, A, Bf) asm volatile( \
    "mma.sync.aligned.m16n8k16.row.col.f32.bf16.bf16.f32 " \
    "{%0,%1,%2,%3},{%4,%5,%6,%7},{%8,%9},{%0,%1,%2,%3};\n" \
    : "+f"(C[0]), "+f"(C[1]), "+f"(C[2]), "+f"(C[3]) \
    : "r"(A[0]), "r"(A[1]), "r"(A[2]), "r"(A[3]), "r"((Bf)[0]), "r"((Bf)[1]))

#define LDSM4(R, ADDR) asm volatile( \
    "ldmatrix.sync.aligned.m8n8.x4.shared.b16 {%0,%1,%2,%3}, [%4];" \
    : "=r"((R)[0]), "=r"((R)[1]), "=r"((R)[2]), "=r"((R)[3]) : "r"(ADDR))

// ---------------- prep: weight transposes + hi/lo split + counter reset ----------------
__global__ void prep_kernel(const float* __restrict__ W5, const float* __restrict__ U5,
                            const float* __restrict__ W6, const float* __restrict__ U6) {
    int i = blockIdx.x * blockDim.x + threadIdx.x;
    if (i < 16) ((unsigned*)g_ctr2)[i] = 0u;
    const int nW5 = N3 * D1;        // 491520
    const int nU  = N3 * HQ;        // 786432
    if (i < nW5) {
        int n = i / D1, k = i % D1;
        bsplit(W5[k * N3 + n], g_W5t_hi[i], g_W5t_lo[i]);
    } else if (i < nW5 + nU) {
        int j = i - nW5; int n = j / HQ, k = j % HQ;
        bsplit(U5[k * N3 + n], g_U5t_hi[j], g_U5t_lo[j]);
    } else if (i < nW5 + 2 * nU) {
        int j = i - nW5 - nU; int n = j / HQ, k = j % HQ;
        bsplit(W6[k * N3 + n], g_W6t_hi[j], g_W6t_lo[j]);
    } else if (i < nW5 + 3 * nU) {
        int j = i - nW5 - 2 * nU; int n = j / HQ, k = j % HQ;
        bsplit(U6[k * N3 + n], g_U6t_hi[j], g_U6t_lo[j]);
    }
}

// ---------------- build X = concat(repeat(z), x2) * masks, split to bf16 hi/lo ----------------
__global__ void build_x_kernel(const float* __restrict__ z, const float* __restrict__ x2,
                               const float* __restrict__ masks) {
    int i = blockIdx.x * blockDim.x + threadIdx.x;
    if (i >= MROWS * D1) return;
    int row = i / D1, c = i % D1;
    int b = row >> 9;                 // T = 512
    float m = masks[row];
    float v = (c < 256) ? z[b * 256 + c] : x2[(size_t)row * 64 + (c - 256)];
    v *= m;
    bsplit(v, g_Xhi[i], g_Xlo[i]);
}

// ---------------- feedforward GEMM: g_xW = A(hi,lo) @ Wt(hi,lo)^T + bias ----------------
// Grid (24 n-tiles, 512 m-tiles): x-fastest block order puts all n-tiles of a
// small m-stripe in each wave -> A rows hit L2 once and are reused 24x
// (previous (512,24) order re-streamed the 134MB A matrix 24x from DRAM).
// Block tile 128(M) x 64(N), BK=16, 256 threads (8 warps, 4x2, warp tile 32x32)
__global__ void __launch_bounds__(256) gemm_ff(int phase, const float* __restrict__ bias) {
    const int K = phase ? HQ : D1;
    const __nv_bfloat16* Ahi = phase ? g_g5hi : g_Xhi;
    const __nv_bfloat16* Alo = phase ? g_g5lo : g_Xlo;
    const __nv_bfloat16* Whi = phase ? g_W6t_hi : g_W5t_hi;
    const __nv_bfloat16* Wlo = phase ? g_W6t_lo : g_W5t_lo;

    __shared__ __nv_bfloat16 sAh[128 * 24], sAl[128 * 24], sWh[64 * 24], sWl[64 * 24];

    int tid = threadIdx.x;
    int row0 = blockIdx.y * 128, n0 = blockIdx.x * 64;
    int warp = tid >> 5, lane = tid & 31, g = lane >> 2, tg = lane & 3;
    int wm = warp >> 1, wn = warp & 1;
    int r = tid >> 1, h = tid & 1;

    float C[2][4][4];
#pragma unroll
    for (int a = 0; a < 2; a++)
#pragma unroll
        for (int b = 0; b < 4; b++)
#pragma unroll
            for (int c = 0; c < 4; c++) C[a][b][c] = 0.0f;

    const int nk = K / 16;
    uint4 ra, rb, rw, rv;

#define FF_LOAD(KT) do { \
        int k0 = (KT) * 16; \
        ra = *((const uint4*)Ahi + ((size_t)(row0 + r) * K + k0) / 8 + h); \
        rb = *((const uint4*)Alo + ((size_t)(row0 + r) * K + k0) / 8 + h); \
        if (tid < 128) { \
            rw = *((const uint4*)Whi + ((size_t)(n0 + r) * K + k0) / 8 + h); \
            rv = *((const uint4*)Wlo + ((size_t)(n0 + r) * K + k0) / 8 + h); \
        } \
    } while (0)

    FF_LOAD(0);
    for (int kt = 0; kt < nk; kt++) {
        // stage current tile from regs
        *(uint4*)((char*)sAh + r * 48 + h * 16) = ra;
        *(uint4*)((char*)sAl + r * 48 + h * 16) = rb;
        if (tid < 128) {
            *(uint4*)((char*)sWh + r * 48 + h * 16) = rw;
            *(uint4*)((char*)sWl + r * 48 + h * 16) = rv;
        }
        __syncthreads();
        if (kt + 1 < nk) FF_LOAD(kt + 1);   // overlaps MMAs below

        uint32_t ah[2][4], al[2][4], bh[4][2], bl[4][2];
#pragma unroll
        for (int mt = 0; mt < 2; mt++) {
            int m = wm * 32 + mt * 16 + g;
            ah[mt][0] = *(uint32_t*)((char*)sAh + m * 48 + tg * 4);
            ah[mt][1] = *(uint32_t*)((char*)sAh + (m + 8) * 48 + tg * 4);
            ah[mt][2] = *(uint32_t*)((char*)sAh + m * 48 + 16 + tg * 4);
            ah[mt][3] = *(uint32_t*)((char*)sAh + (m + 8) * 48 + 16 + tg * 4);
            al[mt][0] = *(uint32_t*)((char*)sAl + m * 48 + tg * 4);
            al[mt][1] = *(uint32_t*)((char*)sAl + (m + 8) * 48 + tg * 4);
            al[mt][2] = *(uint32_t*)((char*)sAl + m * 48 + 16 + tg * 4);
            al[mt][3] = *(uint32_t*)((char*)sAl + (m + 8) * 48 + 16 + tg * 4);
        }
#pragma unroll
        for (int nt = 0; nt < 4; nt++) {
            int n = wn * 32 + nt * 8 + g;
            bh[nt][0] = *(uint32_t*)((char*)sWh + n * 48 + tg * 4);
            bh[nt][1] = *(uint32_t*)((char*)sWh + n * 48 + 16 + tg * 4);
            bl[nt][0] = *(uint32_t*)((char*)sWl + n * 48 + tg * 4);
            bl[nt][1] = *(uint32_t*)((char*)sWl + n * 48 + 16 + tg * 4);
        }
#pragma unroll
        for (int mt = 0; mt < 2; mt++)
#pragma unroll
            for (int nt = 0; nt < 4; nt++) {
                MMA16816(C[mt][nt], ah[mt], bh[nt]);
                MMA16816(C[mt][nt], ah[mt], bl[nt]);
                MMA16816(C[mt][nt], al[mt], bh[nt]);
            }
        __syncthreads();
    }
    // epilogue: + bias, store fp32
#pragma unroll
    for (int mt = 0; mt < 2; mt++) {
#pragma unroll
        for (int nt = 0; nt < 4; nt++) {
            int m = row0 + wm * 32 + mt * 16 + g;
            int n = n0 + wn * 32 + nt * 8 + tg * 2;
            float b0v = bias[n], b1v = bias[n + 1];
            g_xW[(size_t)m * N3 + n]           = C[mt][nt][0] + b0v;
            g_xW[(size_t)m * N3 + n + 1]       = C[mt][nt][1] + b1v;
            g_xW[(size_t)(m + 8) * N3 + n]     = C[mt][nt][2] + b0v;
            g_xW[(size_t)(m + 8) * N3 + n + 1] = C[mt][nt][3] + b1v;
        }
    }
}

// ---------------- persistent GRU recurrence ----------------
// 128 blocks (8 batch tiles x 16 feature tiles), 384 threads (12 warps), 1 block/SM.
// Warp partition: ks (K half, 2) x gate (3) x n-half (2x16 cols).
// Fragments via ldmatrix.x4; two K-partials combined through smem inner buffers.
// smem: U hi (98304) | U lo (98304) | hs hi (16384) | hs lo (16384, aliased by inner[2])
#define SM_UHI 0
#define SM_ULO 98304
#define SM_HSH 196608
#define SM_HSL 212992
#define SM_TOTAL 229376
#define INNER_STRIDE 100
#define INNER_BYTES  6400     // 16 rows * 100 floats * 4

__global__ void __launch_bounds__(384, 1) gru_rec(int phase, const float* __restrict__ br) {
    extern __shared__ char sm[];
    const __nv_bfloat16* Uth = phase ? g_U6t_hi : g_U5t_hi;
    const __nv_bfloat16* Utl = phase ? g_U6t_lo : g_U5t_lo;
    const float* __restrict__ xW = g_xW;
    __nv_bfloat16* Ghi = phase ? g_g6hi : g_g5hi;
    __nv_bfloat16* Glo = phase ? g_g6lo : g_g5lo;

    const int tid = threadIdx.x;
    const int warp = tid >> 5, lane = tid & 31;
    const int g = lane >> 2, tg = lane & 3;
    const int bb = (int)blockIdx.x >> 4, fb = (int)blockIdx.x & 15;
    const int b0 = bb * 16, f0 = fb * 32;
    unsigned* ctr = &g_ctr2[phase][bb];

    // warp roles
    const int ks  = warp / 6;            // K half: kt in [ks*16, ks*16+16)
    const int w6  = warp % 6;
    const int gi2 = w6 >> 1;             // gate 0..2
    const int nh  = w6 & 1;              // n half (16 cols)
    const int rm  = lane & 7;
    const int jq  = lane >> 3;           // ldmatrix matrix id 0..3
    const int arow = rm + ((jq & 1) << 3);       // A: j0/j2 rows 0-7, j1/j3 rows 8-15
    const int ahh  = jq >> 1;                    // A: k half
    const int brow = rm + ((jq >> 1) << 3);      // B: j0/j1 n 0-7, j2/j3 n 8-15
    const int bkk  = jq & 1;                     // B: k half
    const int jrow0 = gi2 * 32 + nh * 16;

    const unsigned sm32 = (unsigned)__cvta_generic_to_shared(sm);
    const unsigned aBaseH = sm32 + SM_HSH + arow * 1024;
    const unsigned aBaseL = sm32 + SM_HSL + arow * 1024;
    const unsigned bBaseH = sm32 + SM_UHI + (jrow0 + brow) * 1024;
    const unsigned bBaseL = sm32 + SM_ULO + (jrow0 + brow) * 1024;

    // ---- preload U slice: 96 rows (3 gates x 32 cols) x 512 K, hi+lo, 16B-chunk swizzle
    for (int idx = tid; idx < 2 * 96 * 64; idx += 384) {
        int arr = idx >= 96 * 64;
        int e = arr ? (idx - 96 * 64) : idx;
        int j = e >> 6;              // smem row 0..95
        int q = e & 63;              // 16B chunk within row
        int sw = q ^ (j & 7);
        int n = (j >> 5) * HQ + f0 + (j & 31);   // global col in 0..1535
        uint4 v = ((const uint4*)((arr ? Utl : Uth) + (size_t)n * HQ))[q];
        *(uint4*)(sm + (arr ? SM_ULO : SM_UHI) + j * 1024 + sw * 16) = v;
    }
    // per-thread combine constants (biases)
    float bzv[2], brv[2], bhv[2];
#pragma unroll
    for (int s = 0; s < 2; s++) {
        int e = tid + s * 384;
        if (e < 512) {
            int f = f0 + (e & 31);
            bzv[s] = br[f]; brv[s] = br[512 + f]; bhv[s] = br[1024 + f];
        } else { bzv[s] = brv[s] = bhv[s] = 0.f; }
    }
    __syncthreads();

    // ---- preload xW for t = 0 (persistent registers; refreshed each step under the barrier)
    float xzv[2], xrv[2], xhv[2], hpv[2];
#pragma unroll
    for (int s = 0; s < 2; s++) {
        int e = tid + s * 384;
        if (e < 512) {
            int r = e >> 5, c = e & 31;
            size_t row = (size_t)(b0 + r) * TQ;
            int f = f0 + c;
            xzv[s] = xW[row * N3 + f];
            xrv[s] = xW[row * N3 + 512 + f];
            xhv[s] = xW[row * N3 + 1024 + f];
        } else { xzv[s] = xrv[s] = xhv[s] = 0.f; }
    }

    for (int t = 0; t < TQ; t++) {
        // ---- stage h_{t-1}: 16 rows x 512 bf16, hi+lo
        if (t == 0) {
            for (int idx = tid; idx < 2048; idx += 384) {
                int arr = idx >> 10, e = idx & 1023, r = e >> 6, q = e & 63;
                int sw = q ^ (r & 7);
                *(uint4*)(sm + (arr ? SM_HSL : SM_HSH) + r * 1024 + sw * 16) =
                    make_uint4(0u, 0u, 0u, 0u);
            }
        } else {
            for (int idx = tid; idx < 2048; idx += 384) {
                int arr = idx >> 10, e = idx & 1023, r = e >> 6, q = e & 63;
                int sw = q ^ (r & 7);
                const __nv_bfloat16* src =
                    (arr ? Glo : Ghi) + ((size_t)(b0 + r) * TQ + (t - 1)) * HQ;
                uint4 v = __ldcg((const uint4*)src + q);
                *(uint4*)(sm + (arr ? SM_HSL : SM_HSH) + r * 1024 + sw * 16) = v;
            }
        }
        __syncthreads();

        // ---- h_prev values for the blend (global feature index f0+c)
#pragma unroll
        for (int s = 0; s < 2; s++) {
            int e = tid + s * 384;
            hpv[s] = 0.f;
            if (e < 512) {
                int r = e >> 5, c = e & 31;
                int w = (f0 + c) >> 1;
                int sw = w ^ ((r & 7) << 2);
                uint32_t whi = *(uint32_t*)(sm + SM_HSH + r * 1024 + sw * 4);
                uint32_t wlo = *(uint32_t*)(sm + SM_HSL + r * 1024 + sw * 4);
                unsigned short sh = (c & 1) ? (unsigned short)(whi >> 16) : (unsigned short)(whi & 0xffff);
                unsigned short sl = (c & 1) ? (unsigned short)(wlo >> 16) : (unsigned short)(wlo & 0xffff);
                hpv[s] = __bfloat162float(__ushort_as_bfloat16(sh)) +
                         __bfloat162float(__ushort_as_bfloat16(sl));
            }
        }

        // ---- MMA: partial inner[16 x 96] over my K half (3-pass bf16 split, ldmatrix)
        float C0[4] = {0.f, 0.f, 0.f, 0.f}, C1[4] = {0.f, 0.f, 0.f, 0.f};
        const int ktBeg = ks * 16, ktEnd = ktBeg + 16;
#pragma unroll 4
        for (int kt = ktBeg; kt < ktEnd; kt++) {
            unsigned aOff = (unsigned)(((2 * kt + ahh) ^ rm) * 16);
            unsigned bOff = (unsigned)(((2 * kt + bkk) ^ rm) * 16);
            uint32_t ah4[4], al4[4], bh4[4], bl4[4];
            LDSM4(ah4, aBaseH + aOff);
            LDSM4(al4, aBaseL + aOff);
            LDSM4(bh4, bBaseH + bOff);
            LDSM4(bl4, bBaseL + bOff);
            MMA16816(C0, ah4, bh4);
            MMA16816(C0, ah4, bl4);
            MMA16816(C0, al4, bh4);
            MMA16816(C1, ah4, bh4 + 2);
            MMA16816(C1, ah4, bl4 + 2);
            MMA16816(C1, al4, bh4 + 2);
        }
        __syncthreads();   // all reads of hs done (hprev + ldmatrix)

        // ---- exchange: write K-partials into inner buffers aliased over hs_lo
        {
            float* innerK = (float*)(sm + SM_HSL + ks * INNER_BYTES);
            int colb = gi2 * 32 + nh * 16 + 2 * tg;
            innerK[g * INNER_STRIDE + colb]            = C0[0];
            innerK[g * INNER_STRIDE + colb + 1]        = C0[1];
            innerK[(g + 8) * INNER_STRIDE + colb]      = C0[2];
            innerK[(g + 8) * INNER_STRIDE + colb + 1]  = C0[3];
            innerK[g * INNER_STRIDE + colb + 8]        = C1[0];
            innerK[g * INNER_STRIDE + colb + 9]        = C1[1];
            innerK[(g + 8) * INNER_STRIDE + colb + 8]  = C1[2];
            innerK[(g + 8) * INNER_STRIDE + colb + 9]  = C1[3];
        }
        __syncthreads();

        // ---- gates + h_new, write to gmem (time-indexed: no WAR)
#pragma unroll
        for (int s = 0; s < 2; s++) {
            int e = tid + s * 384;
            if (e < 512) {
                int r = e >> 5, c = e & 31;
                const float* in0 = (const float*)(sm + SM_HSL);
                const float* in1 = (const float*)(sm + SM_HSL + INNER_BYTES);
                float iz = in0[r * INNER_STRIDE + c]      + in1[r * INNER_STRIDE + c];
                float ir = in0[r * INNER_STRIDE + 32 + c] + in1[r * INNER_STRIDE + 32 + c];
                float ih = in0[r * INNER_STRIDE + 64 + c] + in1[r * INNER_STRIDE + 64 + c];
                float zg = hsig(xzv[s] + iz + bzv[s]);
                float rg = hsig(xrv[s] + ir + brv[s]);
                float hh = tanhf(xhv[s] + rg * (ih + bhv[s]));
                float hn = zg * hpv[s] + (1.0f - zg) * hh;
                size_t row = (size_t)(b0 + r) * TQ + t;
                __nv_bfloat16 hi, lo; bsplit(hn, hi, lo);
                Ghi[row * HQ + f0 + c] = hi;
                Glo[row * HQ + f0 + c] = lo;
            }
        }

        // ---- prefetch xW for t+1 (h-independent; latency hides under the barrier wait)
        if (t + 1 < TQ) {
#pragma unroll
            for (int s = 0; s < 2; s++) {
                int e = tid + s * 384;
                if (e < 512) {
                    int r = e >> 5, c = e & 31;
                    size_t row = (size_t)(b0 + r) * TQ + (t + 1);
                    int f = f0 + c;
                    xzv[s] = xW[row * N3 + f];
                    xrv[s] = xW[row * N3 + 512 + f];
                    xhv[s] = xW[row * N3 + 1024 + f];
                }
            }
        }

        __syncthreads();                  // all h stores issued before publication
        // ---- per-batch-group barrier: release-add + acquire spin (no threadfence)
        if (tid == 0) {
            asm volatile("red.release.gpu.global.add.u32 [%0], %1;" :: "l"(ctr), "r"(1u) : "memory");
            unsigned target = (unsigned)(t + 1) * 16u;
            unsigned v;
            do {
                asm volatile("ld.acquire.gpu.u32 %0, [%1];" : "=r"(v) : "l"(ctr));
                if (v >= target) break;
                __nanosleep(16);
            } while (true);
        }
        __syncthreads();
    }
}

// ---------------- final dense(1) + tanh + mask ----------------
__global__ void __launch_bounds__(256) dense_out(const float* __restrict__ Wd,
                                                 const float* __restrict__ bd,
                                                 const float* __restrict__ dmask,
                                                 float* __restrict__ out) {
    __shared__ float w[512];
    int tid = threadIdx.x;
    for (int i = tid; i < 512; i += 256) w[i] = Wd[i];
    __syncthreads();
    int warp = tid >> 5, lane = tid & 31;
    size_t row = (size_t)blockIdx.x * 8 + warp;
    const __nv_bfloat16* ph = g_g6hi + row * HQ;
    const __nv_bfloat16* pl = g_g6lo + row * HQ;
    float s = 0.f;
#pragma unroll 4
    for (int i = lane; i < 512; i += 32)
        s += (__bfloat162float(ph[i]) + __bfloat162float(pl[i])) * w[i];
#pragma unroll
    for (int o = 16; o; o >>= 1) s += __shfl_xor_sync(0xffffffffu, s, o);
    if (lane == 0) out[row] = tanhf(s + bd[0]) * dmask[row];
}

// ---------------- launch ----------------
extern "C" void kernel_launch(void* const* d_in, const int* in_sizes, int n_in,
                              void* d_out, int out_size) {
    const float* z   = (const float*)d_in[0];
    const float* x2  = (const float*)d_in[1];
    const float* msk = (const float*)d_in[2];
    const float* dmk = (const float*)d_in[3];
    const float* W5  = (const float*)d_in[4];
    const float* U5  = (const float*)d_in[5];
    const float* bi5 = (const float*)d_in[6];
    const float* br5 = (const float*)d_in[7];
    const float* W6  = (const float*)d_in[8];
    const float* U6  = (const float*)d_in[9];
    const float* bi6 = (const float*)d_in[10];
    const float* br6 = (const float*)d_in[11];
    const float* Wd  = (const float*)d_in[12];
    const float* bd  = (const float*)d_in[13];
    float* out = (float*)d_out;

    cudaFuncSetAttribute(gru_rec, cudaFuncAttributeMaxDynamicSharedMemorySize, SM_TOTAL);

    prep_kernel<<<11136, 256>>>(W5, U5, W6, U6);
    build_x_kernel<<<81920, 256>>>(z, x2, msk);
    gemm_ff<<<dim3(24, 512), 256>>>(0, bi5);
    gru_rec<<<128, 384, SM_TOTAL>>>(0, br5);
    gemm_ff<<<dim3(24, 512), 256>>>(1, bi6);
    gru_rec<<<128, 384, SM_TOTAL>>>(1, br6);
    dense_out<<<8192, 256>>>(Wd, bd, dmk, out);
}